// round 1
// baseline (speedup 1.0000x reference)
#include <cuda_runtime.h>

#define NN 50000
#define EE 800000
// dims: IN=OUT=64, H=8, HD=8

// ---------------- device scratch (allocation-free) ----------------
__device__ float g_Q[NN * 64];
__device__ float g_K[NN * 64];
__device__ float g_V[NN * 64];
__device__ float g_Eh[EE * 64];
__device__ float g_wV[NN * 64];
__device__ float g_Z[NN * 8];
__device__ float g_h1[NN * 64];   // pre-BN1 (x + attn@O_w + O_b)
__device__ float g_h2[NN * 64];   // pre-BN2 (bn1_out + ffn)
__device__ float g_stats[256];    // [sum1(64) | sumsq1(64) | sum2(64) | sumsq2(64)]

// ---------------- f32x2 helpers (FFMA2: 2x fp32 FMA per instr) ----------------
__device__ __forceinline__ unsigned long long pack2(float v) {
    unsigned long long r;
    asm("mov.b64 %0, {%1, %1};" : "=l"(r) : "f"(v));
    return r;
}
__device__ __forceinline__ void fma2(unsigned long long& acc, unsigned long long a,
                                     unsigned long long b) {
    asm("fma.rn.f32x2 %0, %1, %2, %0;" : "+l"(acc) : "l"(a), "l"(b));
}
__device__ __forceinline__ float2 unpack2(unsigned long long v) {
    float2 r;
    asm("mov.b64 {%0, %1}, %2;" : "=f"(r.x), "=f"(r.y) : "l"(v));
    return r;
}
__device__ __forceinline__ void red4(float* p, float a, float b, float c, float d) {
    asm volatile("red.global.add.v4.f32 [%0], {%1, %2, %3, %4};"
                 :: "l"(p), "f"(a), "f"(b), "f"(c), "f"(d) : "memory");
}

// ---------------- zero accumulators ----------------
__global__ __launch_bounds__(256) void zero_kernel() {
    int idx = blockIdx.x * 256 + threadIdx.x;
    int stride = gridDim.x * 256;
    for (int i = idx; i < NN * 64; i += stride) g_wV[i] = 0.0f;
    for (int i = idx; i < NN * 8; i += stride) g_Z[i] = 0.0f;
    if (idx < 256) g_stats[idx] = 0.0f;
}

// ---------------- generic M x 64 @ 64 x 64 GEMM (dest selected at compile time) ----
// DST: 0=g_Q 1=g_K 2=g_V 3=g_Eh
template <int DST>
__global__ __launch_bounds__(256) void gemm64_kernel(const float* __restrict__ A,
                                                     const float* __restrict__ W, int M) {
    float* C = (DST == 0) ? g_Q : (DST == 1) ? g_K : (DST == 2) ? g_V : g_Eh;
    __shared__ float sW[4096];
    __shared__ float sA[16][64];
    int t = threadIdx.x;
    for (int i = t; i < 4096; i += 256) sW[i] = W[i];
    int cg = t & 15;   // 4-column group: cols cg*4 .. cg*4+3
    int rr = t >> 4;   // row within 16-row tile
    const ulonglong2* sW2 = (const ulonglong2*)sW;
    __syncthreads();
    for (int base = blockIdx.x * 16; base < M; base += gridDim.x * 16) {
#pragma unroll
        for (int ii = 0; ii < 4; ii++) {
            int idx = t + ii * 256;
            sA[idx >> 6][idx & 63] = A[base * 64 + idx];
        }
        __syncthreads();
        unsigned long long a01 = 0ull, a23 = 0ull;
#pragma unroll
        for (int k = 0; k < 64; k++) {
            unsigned long long xx = pack2(sA[rr][k]);
            ulonglong2 w = sW2[k * 16 + cg];
            fma2(a01, w.x, xx);
            fma2(a23, w.y, xx);
        }
        float2 lo = unpack2(a01), hi = unpack2(a23);
        float4 out = make_float4(lo.x, lo.y, hi.x, hi.y);
        ((float4*)C)[(base + rr) * 16 + cg] = out;
        __syncthreads();
    }
}

// ---------------- edge scoring + scatter ----------------
__global__ __launch_bounds__(256) void edge_kernel(const int* __restrict__ ei) {
    int t = threadIdx.x;
    int i = t & 15;         // 16 lanes per edge; lane covers 4 cols
    int eg = t >> 4;        // 16 edges per block-iteration
    int c4 = i * 4;
    int h = i >> 1;         // head (two lanes per head)
    const float inv = 0.35355339059327373f;  // 1/sqrt(8)
    for (int base = blockIdx.x * 16; base < EE; base += gridDim.x * 16) {
        int e = base + eg;
        int src = ei[e];
        int dst = ei[EE + e];
        float4 eh = ((const float4*)g_Eh)[e * 16 + i];
        float4 kk = ((const float4*)g_K)[src * 16 + i];
        float4 qq = ((const float4*)g_Q)[dst * 16 + i];
        float4 vv = ((const float4*)g_V)[src * 16 + i];
        float p = eh.x * kk.x * qq.x + eh.y * kk.y * qq.y +
                  eh.z * kk.z * qq.z + eh.w * kk.w * qq.w;
        p += __shfl_xor_sync(0xffffffffu, p, 1);
        float s = p * inv;
        s = fminf(fmaxf(s, -5.0f), 5.0f);
        float sc = __expf(s);
        red4(&g_wV[dst * 64 + c4], vv.x * sc, vv.y * sc, vv.z * sc, vv.w * sc);
        if ((i & 1) == 0) atomicAdd(&g_Z[dst * 8 + h], sc);
    }
}

// ---------------- attn normalize + O projection + residual + BN1 stats ----------------
__global__ __launch_bounds__(256) void attn_out_kernel(const float* __restrict__ x,
                                                       const float* __restrict__ Ow,
                                                       const float* __restrict__ Ob) {
    __shared__ float sW[4096];
    __shared__ float sA[16][64];
    __shared__ float ssum[64], ssq[64];
    int t = threadIdx.x;
    for (int i = t; i < 4096; i += 256) sW[i] = Ow[i];
    if (t < 64) { ssum[t] = 0.0f; ssq[t] = 0.0f; }
    int cg = t & 15, rr = t >> 4;
    float4 ob = ((const float4*)Ob)[cg];
    const ulonglong2* sW2 = (const ulonglong2*)sW;
    float4 lsum = make_float4(0, 0, 0, 0), lsq = make_float4(0, 0, 0, 0);
    __syncthreads();
    for (int base = blockIdx.x * 16; base < NN; base += gridDim.x * 16) {
#pragma unroll
        for (int ii = 0; ii < 4; ii++) {
            int idx = t + ii * 256;
            int r2 = idx >> 6, k = idx & 63;
            int row = base + r2;
            sA[r2][k] = g_wV[row * 64 + k] / (g_Z[row * 8 + (k >> 3)] + 1e-6f);
        }
        __syncthreads();
        unsigned long long a01 = 0ull, a23 = 0ull;
#pragma unroll
        for (int k = 0; k < 64; k++) {
            unsigned long long xx = pack2(sA[rr][k]);
            ulonglong2 w = sW2[k * 16 + cg];
            fma2(a01, w.x, xx);
            fma2(a23, w.y, xx);
        }
        float2 lo = unpack2(a01), hi = unpack2(a23);
        float4 xr = ((const float4*)x)[(base + rr) * 16 + cg];
        float4 hv;
        hv.x = lo.x + ob.x + xr.x;
        hv.y = lo.y + ob.y + xr.y;
        hv.z = hi.x + ob.z + xr.z;
        hv.w = hi.y + ob.w + xr.w;
        ((float4*)g_h1)[(base + rr) * 16 + cg] = hv;
        lsum.x += hv.x; lsum.y += hv.y; lsum.z += hv.z; lsum.w += hv.w;
        lsq.x += hv.x * hv.x; lsq.y += hv.y * hv.y;
        lsq.z += hv.z * hv.z; lsq.w += hv.w * hv.w;
        __syncthreads();
    }
    int c0 = cg * 4;
    atomicAdd(&ssum[c0 + 0], lsum.x); atomicAdd(&ssum[c0 + 1], lsum.y);
    atomicAdd(&ssum[c0 + 2], lsum.z); atomicAdd(&ssum[c0 + 3], lsum.w);
    atomicAdd(&ssq[c0 + 0], lsq.x);   atomicAdd(&ssq[c0 + 1], lsq.y);
    atomicAdd(&ssq[c0 + 2], lsq.z);   atomicAdd(&ssq[c0 + 3], lsq.w);
    __syncthreads();
    if (t < 64) {
        atomicAdd(&g_stats[t], ssum[t]);
        atomicAdd(&g_stats[64 + t], ssq[t]);
    }
}

// ---------------- BN1 apply + FFN + residual + BN2 stats ----------------
__global__ __launch_bounds__(256) void ffn_kernel(const float* __restrict__ f1w,
                                                  const float* __restrict__ f1b,
                                                  const float* __restrict__ f2w,
                                                  const float* __restrict__ f2b,
                                                  const float* __restrict__ bn1g,
                                                  const float* __restrict__ bn1b) {
    __shared__ float sF1[64 * 128];  // 32 KB
    __shared__ float sH[8][64];
    __shared__ float sT[8][128];
    __shared__ float sMu[64], sRs[64], sG[64], sB[64], sB1[128];
    __shared__ float ssum[64], ssq[64];
    int t = threadIdx.x;
    for (int i = t; i < 8192; i += 256) sF1[i] = f1w[i];
    if (t < 64) {
        float su = g_stats[t], sq = g_stats[64 + t];
        float mu = su * (1.0f / NN);
        float var = sq * (1.0f / NN) - mu * mu;
        sMu[t] = mu;
        sRs[t] = rsqrtf(var + 1e-5f);
        sG[t] = bn1g[t];
        sB[t] = bn1b[t];
        ssum[t] = 0.0f;
        ssq[t] = 0.0f;
    }
    if (t < 128) sB1[t] = f1b[t];
    __syncthreads();
    int jg = t & 31, nn = t >> 5;  // nn: node slot 0..7
    float2 f2bv = ((const float2*)f2b)[jg];
    const ulonglong2* F1 = (const ulonglong2*)sF1;
    const unsigned long long* F2 = (const unsigned long long*)f2w;
    float2 ls = make_float2(0, 0), lq = make_float2(0, 0);
    for (int base = blockIdx.x * 8; base < NN; base += gridDim.x * 8) {
#pragma unroll
        for (int ii = 0; ii < 2; ii++) {
            int idx = t + ii * 256;
            int n = idx >> 6, c = idx & 63;
            float hv = g_h1[(base + n) * 64 + c];
            sH[n][c] = sG[c] * (hv - sMu[c]) * sRs[c] + sB[c];
        }
        __syncthreads();
        // phase B: t_hidden[nn][jg*4 .. +3] = relu(hbn @ f1_w + f1_b)
        {
            unsigned long long a01 = 0ull, a23 = 0ull;
#pragma unroll
            for (int k = 0; k < 64; k++) {
                unsigned long long xx = pack2(sH[nn][k]);
                ulonglong2 w = F1[k * 32 + jg];
                fma2(a01, w.x, xx);
                fma2(a23, w.y, xx);
            }
            float2 lo = unpack2(a01), hi = unpack2(a23);
            int j0 = jg * 4;
            float4 tv;
            tv.x = fmaxf(lo.x + sB1[j0 + 0], 0.0f);
            tv.y = fmaxf(lo.y + sB1[j0 + 1], 0.0f);
            tv.z = fmaxf(hi.x + sB1[j0 + 2], 0.0f);
            tv.w = fmaxf(hi.y + sB1[j0 + 3], 0.0f);
            *(float4*)&sT[nn][j0] = tv;
        }
        __syncthreads();
        // phase C: out[nn][jg*2 .. +1] = t @ f2_w + f2_b + hbn  (residual 2)
        {
            unsigned long long a01 = 0ull;
#pragma unroll
            for (int k = 0; k < 128; k++) {
                unsigned long long xx = pack2(sT[nn][k]);
                fma2(a01, F2[k * 32 + jg], xx);
            }
            float2 o = unpack2(a01);
            int col = jg * 2;
            float2 hb = *(float2*)&sH[nn][col];
            o.x += f2bv.x + hb.x;
            o.y += f2bv.y + hb.y;
            *(float2*)&g_h2[(base + nn) * 64 + col] = o;
            ls.x += o.x; ls.y += o.y;
            lq.x += o.x * o.x; lq.y += o.y * o.y;
        }
        __syncthreads();
    }
    int col = jg * 2;
    atomicAdd(&ssum[col], ls.x);     atomicAdd(&ssum[col + 1], ls.y);
    atomicAdd(&ssq[col], lq.x);      atomicAdd(&ssq[col + 1], lq.y);
    __syncthreads();
    if (t < 64) {
        atomicAdd(&g_stats[128 + t], ssum[t]);
        atomicAdd(&g_stats[192 + t], ssq[t]);
    }
}

// ---------------- BN2 apply -> output ----------------
__global__ __launch_bounds__(256) void bn2_kernel(const float* __restrict__ bn2g,
                                                  const float* __restrict__ bn2b,
                                                  float* __restrict__ out) {
    int tid = blockIdx.x * 256 + threadIdx.x;  // over NN*16 float4 groups
    int i = tid & 15;
    int c0 = i * 4;
    float4 g = ((const float4*)bn2g)[i];
    float4 b = ((const float4*)bn2b)[i];
    float4 v = ((const float4*)g_h2)[tid];
    float4 o;
#pragma unroll
    for (int j = 0; j < 4; j++) {
        int c = c0 + j;
        float mu = g_stats[128 + c] * (1.0f / NN);
        float var = g_stats[192 + c] * (1.0f / NN) - mu * mu;
        float rs = rsqrtf(var + 1e-5f);
        float* vp = (&v.x) + j;
        float* op = (&o.x) + j;
        float* gp = (&g.x) + j;
        float* bp = (&b.x) + j;
        *op = (*gp) * ((*vp) - mu) * rs + (*bp);
    }
    ((float4*)out)[tid] = o;
}

// ---------------- host launcher ----------------
extern "C" void kernel_launch(void* const* d_in, const int* in_sizes, int n_in,
                              void* d_out, int out_size) {
    const float *x = nullptr, *edge_attr = nullptr;
    const float *Wq = nullptr, *Wk = nullptr, *We = nullptr, *Wv = nullptr, *Ow = nullptr;
    const float *Ob = nullptr, *f1w = nullptr, *f1b = nullptr, *f2w = nullptr, *f2b = nullptr;
    const float *bn1g = nullptr, *bn1b = nullptr, *bn2g = nullptr, *bn2b = nullptr;
    const int* ei = nullptr;
    int c4096 = 0, c8192 = 0, c64 = 0;
    for (int i = 0; i < n_in; i++) {
        int s = in_sizes[i];
        const void* p = d_in[i];
        if (s == NN * 64) x = (const float*)p;
        else if (s == EE * 64) edge_attr = (const float*)p;
        else if (s == 2 * EE) ei = (const int*)p;
        else if (s == 4096) {
            const float* f = (const float*)p;
            if (c4096 == 0) Wq = f;
            else if (c4096 == 1) Wk = f;
            else if (c4096 == 2) We = f;
            else if (c4096 == 3) Wv = f;
            else Ow = f;
            c4096++;
        } else if (s == 8192) {
            if (c8192 == 0) f1w = (const float*)p;
            else f2w = (const float*)p;
            c8192++;
        } else if (s == 128) {
            f1b = (const float*)p;
        } else if (s == 64) {
            const float* f = (const float*)p;
            if (c64 == 0) Ob = f;
            else if (c64 == 1) f2b = f;
            else if (c64 == 2) bn1g = f;
            else if (c64 == 3) bn1b = f;
            else if (c64 == 4) bn2g = f;
            else bn2b = f;
            c64++;
        }
    }

    zero_kernel<<<1184, 256>>>();
    gemm64_kernel<0><<<1184, 256>>>(x, Wq, NN);
    gemm64_kernel<1><<<1184, 256>>>(x, Wk, NN);
    gemm64_kernel<2><<<1184, 256>>>(x, Wv, NN);
    gemm64_kernel<3><<<1184, 256>>>(edge_attr, We, EE);
    edge_kernel<<<1184, 256>>>(ei);
    attn_out_kernel<<<1184, 256>>>(x, Ow, Ob);
    ffn_kernel<<<1184, 256>>>(f1w, f1b, f2w, f2b, bn1g, bn1b);
    bn2_kernel<<<3125, 256>>>(bn2g, bn2b, (float*)d_out);
}

// round 2
// speedup vs baseline: 1.9610x; 1.9610x over previous
#include <cuda_runtime.h>

#define NN 50000
#define EE 800000
// dims: IN=OUT=64, H=8, HD=8

// ---------------- device scratch (allocation-free) ----------------
__device__ float g_Q[NN * 64];
__device__ float g_K[NN * 64];
__device__ float g_V[NN * 64];
__device__ float g_wV[NN * 64];
__device__ float g_Z[NN * 8];
__device__ float g_Zi[NN * 8];
__device__ float g_h1[NN * 64];   // pre-BN1 (x + attn@O_w + O_b)
__device__ float g_h2[NN * 64];   // pre-BN2 (bn1_out + ffn)
__device__ float g_stats[256];    // [sum1(64) | sumsq1(64) | sum2(64) | sumsq2(64)]

// ---------------- f32x2 helpers (FFMA2: 2x fp32 FMA per instr) ----------------
__device__ __forceinline__ unsigned long long pack2(float v) {
    unsigned long long r;
    asm("mov.b64 %0, {%1, %1};" : "=l"(r) : "f"(v));
    return r;
}
__device__ __forceinline__ void fma2(unsigned long long& acc, unsigned long long a,
                                     unsigned long long b) {
    asm("fma.rn.f32x2 %0, %1, %2, %0;" : "+l"(acc) : "l"(a), "l"(b));
}
__device__ __forceinline__ float2 unpack2(unsigned long long v) {
    float2 r;
    asm("mov.b64 {%0, %1}, %2;" : "=f"(r.x), "=f"(r.y) : "l"(v));
    return r;
}
__device__ __forceinline__ void red4(float* p, float a, float b, float c, float d) {
    asm volatile("red.global.add.v4.f32 [%0], {%1, %2, %3, %4};"
                 :: "l"(p), "f"(a), "f"(b), "f"(c), "f"(d) : "memory");
}

// Stage a 64x64 weight matrix into smem with pair-swizzle:
// float4 chunk q of row k (cols q*4..q*4+3) -> slot k*16 + (q&1)*8 + (q>>1).
// Lane lc (0..7) then reads its 8 columns lc*8..lc*8+7 as two ulonglong2 at
// slots k*16+lc (cols +0..3) and k*16+8+lc (cols +4..7): both 128B-contiguous
// across lanes -> single conflict-free crossbar phase each.
__device__ __forceinline__ void stage_weight(float* sW, const float* W, int t, int nthr) {
    const float4* W4 = (const float4*)W;
    float4* sW4 = (float4*)sW;
    for (int i = t; i < 1024; i += nthr) {
        int k = i >> 4, q = i & 15;
        sW4[k * 16 + (q & 1) * 8 + (q >> 1)] = W4[i];
    }
}

// ---------------- zero accumulators ----------------
__global__ __launch_bounds__(256) void zero_kernel() {
    int idx = blockIdx.x * 256 + threadIdx.x;
    int stride = gridDim.x * 256;
    for (int i = idx; i < NN * 64; i += stride) g_wV[i] = 0.0f;
    for (int i = idx; i < NN * 8; i += stride) g_Z[i] = 0.0f;
    if (idx < 256) g_stats[idx] = 0.0f;
}

// ---------------- fused Q/K/V projection (warp-tiled GEMM) ----------------
__global__ __launch_bounds__(128, 3) void qkv_kernel(const float* __restrict__ x,
                                                     const float* __restrict__ Wq,
                                                     const float* __restrict__ Wk,
                                                     const float* __restrict__ Wv) {
    __shared__ float sW[3][4096];
    int t = threadIdx.x;
    stage_weight(sW[0], Wq, t, 128);
    stage_weight(sW[1], Wk, t, 128);
    stage_weight(sW[2], Wv, t, 128);
    __syncthreads();
    int warp = t >> 5, lane = t & 31;
    int lr = lane >> 3, lc = lane & 7;
    int tile = blockIdx.x * 4 + warp;
    if (tile >= (NN + 31) / 32) return;
    int row0 = tile * 32 + lr * 8;
    const float4* A4 = (const float4*)x;
    for (int wsel = 0; wsel < 3; wsel++) {
        float* C = (wsel == 0) ? g_Q : (wsel == 1) ? g_K : g_V;
        const ulonglong2* sWu = (const ulonglong2*)sW[wsel];
        unsigned long long acc[8][4] = {};
        for (int kc = 0; kc < 64; kc += 4) {
            float4 a[8];
#pragma unroll
            for (int i = 0; i < 8; i++) {
                int r = row0 + i;
                a[i] = (r < NN) ? A4[r * 16 + (kc >> 2)] : make_float4(0, 0, 0, 0);
            }
#pragma unroll
            for (int kk = 0; kk < 4; kk++) {
                ulonglong2 wlo = sWu[(kc + kk) * 16 + lc];
                ulonglong2 whi = sWu[(kc + kk) * 16 + 8 + lc];
#pragma unroll
                for (int i = 0; i < 8; i++) {
                    unsigned long long ax = pack2((&a[i].x)[kk]);
                    fma2(acc[i][0], wlo.x, ax);
                    fma2(acc[i][1], wlo.y, ax);
                    fma2(acc[i][2], whi.x, ax);
                    fma2(acc[i][3], whi.y, ax);
                }
            }
        }
#pragma unroll
        for (int i = 0; i < 8; i++) {
            int r = row0 + i;
            if (r < NN) {
                float2 c01 = unpack2(acc[i][0]), c23 = unpack2(acc[i][1]);
                float2 c45 = unpack2(acc[i][2]), c67 = unpack2(acc[i][3]);
                ((float4*)C)[r * 16 + lc * 2] = make_float4(c01.x, c01.y, c23.x, c23.y);
                ((float4*)C)[r * 16 + lc * 2 + 1] = make_float4(c45.x, c45.y, c67.x, c67.y);
            }
        }
    }
}

// ---------------- fused edge kernel: Eh GEMM + scoring + scatter ----------------
// Warp tile = 32 edges x 64 cols; lane = 8 edges x 8 cols. Lane's 8 cols = head lc.
__global__ __launch_bounds__(128, 3) void edge_fused_kernel(const float* __restrict__ EA,
                                                            const float* __restrict__ We,
                                                            const int* __restrict__ ei) {
    __shared__ float sW[4096];
    int t = threadIdx.x;
    stage_weight(sW, We, t, 128);
    __syncthreads();
    int warp = t >> 5, lane = t & 31;
    int lr = lane >> 3, lc = lane & 7;
    int tile = blockIdx.x * 4 + warp;   // 25000 tiles exactly
    int e0 = tile * 32 + lr * 8;
    const ulonglong2* sWu = (const ulonglong2*)sW;
    const float4* A4 = (const float4*)EA;
    unsigned long long acc[8][4] = {};
    for (int kc = 0; kc < 64; kc += 4) {
        float4 a[8];
#pragma unroll
        for (int i = 0; i < 8; i++) a[i] = A4[(e0 + i) * 16 + (kc >> 2)];
#pragma unroll
        for (int kk = 0; kk < 4; kk++) {
            ulonglong2 wlo = sWu[(kc + kk) * 16 + lc];
            ulonglong2 whi = sWu[(kc + kk) * 16 + 8 + lc];
#pragma unroll
            for (int i = 0; i < 8; i++) {
                unsigned long long ax = pack2((&a[i].x)[kk]);
                fma2(acc[i][0], wlo.x, ax);
                fma2(acc[i][1], wlo.y, ax);
                fma2(acc[i][2], whi.x, ax);
                fma2(acc[i][3], whi.y, ax);
            }
        }
    }
    const float4* K4 = (const float4*)g_K;
    const float4* Q4 = (const float4*)g_Q;
    const float4* V4 = (const float4*)g_V;
    const float inv = 0.35355339059327373f;  // 1/sqrt(8)
#pragma unroll
    for (int i = 0; i < 8; i++) {
        int e = e0 + i;
        int src = ei[e];
        int dst = ei[EE + e];
        float2 e01 = unpack2(acc[i][0]), e23 = unpack2(acc[i][1]);
        float2 e45 = unpack2(acc[i][2]), e67 = unpack2(acc[i][3]);
        float4 kk0 = K4[src * 16 + lc * 2], kk1 = K4[src * 16 + lc * 2 + 1];
        float4 qq0 = Q4[dst * 16 + lc * 2], qq1 = Q4[dst * 16 + lc * 2 + 1];
        float s = e01.x * kk0.x * qq0.x + e01.y * kk0.y * qq0.y
                + e23.x * kk0.z * qq0.z + e23.y * kk0.w * qq0.w
                + e45.x * kk1.x * qq1.x + e45.y * kk1.y * qq1.y
                + e67.x * kk1.z * qq1.z + e67.y * kk1.w * qq1.w;
        s = fminf(fmaxf(s * inv, -5.0f), 5.0f);
        float sc = __expf(s);
        float4 v0 = V4[src * 16 + lc * 2], v1 = V4[src * 16 + lc * 2 + 1];
        red4(&g_wV[dst * 64 + lc * 8], v0.x * sc, v0.y * sc, v0.z * sc, v0.w * sc);
        red4(&g_wV[dst * 64 + lc * 8 + 4], v1.x * sc, v1.y * sc, v1.z * sc, v1.w * sc);
        atomicAdd(&g_Z[dst * 8 + lc], sc);
    }
}

// ---------------- Z inverse table ----------------
__global__ __launch_bounds__(256) void znorm_kernel() {
    int i = blockIdx.x * 256 + threadIdx.x;
    if (i < NN * 8) g_Zi[i] = 1.0f / (g_Z[i] + 1e-6f);
}

// ---------------- attn normalize + O projection + residual -> g_h1 ----------------
__global__ __launch_bounds__(128, 3) void attn_out_kernel(const float* __restrict__ x,
                                                          const float* __restrict__ Ow,
                                                          const float* __restrict__ Ob) {
    __shared__ float sW[4096];
    int t = threadIdx.x;
    stage_weight(sW, Ow, t, 128);
    __syncthreads();
    int warp = t >> 5, lane = t & 31;
    int lr = lane >> 3, lc = lane & 7;
    int tile = blockIdx.x * 4 + warp;
    if (tile >= (NN + 31) / 32) return;
    int row0 = tile * 32 + lr * 8;
    const ulonglong2* sWu = (const ulonglong2*)sW;
    const float4* wV4 = (const float4*)g_wV;
    unsigned long long acc[8][4] = {};
    for (int kc = 0; kc < 64; kc += 4) {
        float4 a[8];
        int head = kc >> 3;
#pragma unroll
        for (int i = 0; i < 8; i++) {
            int r = row0 + i;
            if (r < NN) {
                float zi = g_Zi[r * 8 + head];
                float4 v = wV4[r * 16 + (kc >> 2)];
                a[i] = make_float4(v.x * zi, v.y * zi, v.z * zi, v.w * zi);
            } else {
                a[i] = make_float4(0, 0, 0, 0);
            }
        }
#pragma unroll
        for (int kk = 0; kk < 4; kk++) {
            ulonglong2 wlo = sWu[(kc + kk) * 16 + lc];
            ulonglong2 whi = sWu[(kc + kk) * 16 + 8 + lc];
#pragma unroll
            for (int i = 0; i < 8; i++) {
                unsigned long long ax = pack2((&a[i].x)[kk]);
                fma2(acc[i][0], wlo.x, ax);
                fma2(acc[i][1], wlo.y, ax);
                fma2(acc[i][2], whi.x, ax);
                fma2(acc[i][3], whi.y, ax);
            }
        }
    }
    float4 ob0 = ((const float4*)Ob)[lc * 2];
    float4 ob1 = ((const float4*)Ob)[lc * 2 + 1];
    const float4* x4 = (const float4*)x;
#pragma unroll
    for (int i = 0; i < 8; i++) {
        int r = row0 + i;
        if (r < NN) {
            float2 c01 = unpack2(acc[i][0]), c23 = unpack2(acc[i][1]);
            float2 c45 = unpack2(acc[i][2]), c67 = unpack2(acc[i][3]);
            float4 xa = x4[r * 16 + lc * 2], xb = x4[r * 16 + lc * 2 + 1];
            float4 o0 = make_float4(c01.x + ob0.x + xa.x, c01.y + ob0.y + xa.y,
                                    c23.x + ob0.z + xa.z, c23.y + ob0.w + xa.w);
            float4 o1 = make_float4(c45.x + ob1.x + xb.x, c45.y + ob1.y + xb.y,
                                    c67.x + ob1.z + xb.z, c67.y + ob1.w + xb.w);
            ((float4*)g_h1)[r * 16 + lc * 2] = o0;
            ((float4*)g_h1)[r * 16 + lc * 2 + 1] = o1;
        }
    }
}

// ---------------- BN1 stats over g_h1 ----------------
__global__ __launch_bounds__(256) void stats1_kernel() {
    __shared__ float ssum[64], ssq[64];
    int t = threadIdx.x;
    if (t < 64) { ssum[t] = 0.0f; ssq[t] = 0.0f; }
    __syncthreads();
    int cg = t & 15;
    float4 s = make_float4(0, 0, 0, 0), q = make_float4(0, 0, 0, 0);
    for (int r = blockIdx.x * 16 + (t >> 4); r < NN; r += gridDim.x * 16) {
        float4 v = ((const float4*)g_h1)[r * 16 + cg];
        s.x += v.x; s.y += v.y; s.z += v.z; s.w += v.w;
        q.x += v.x * v.x; q.y += v.y * v.y; q.z += v.z * v.z; q.w += v.w * v.w;
    }
    int c0 = cg * 4;
    atomicAdd(&ssum[c0 + 0], s.x); atomicAdd(&ssum[c0 + 1], s.y);
    atomicAdd(&ssum[c0 + 2], s.z); atomicAdd(&ssum[c0 + 3], s.w);
    atomicAdd(&ssq[c0 + 0], q.x);  atomicAdd(&ssq[c0 + 1], q.y);
    atomicAdd(&ssq[c0 + 2], q.z);  atomicAdd(&ssq[c0 + 3], q.w);
    __syncthreads();
    if (t < 64) {
        atomicAdd(&g_stats[t], ssum[t]);
        atomicAdd(&g_stats[64 + t], ssq[t]);
    }
}

// ---------------- BN1 apply + FFN + residual + BN2 stats ----------------
__global__ __launch_bounds__(256) void ffn_kernel(const float* __restrict__ f1w,
                                                  const float* __restrict__ f1b,
                                                  const float* __restrict__ f2w,
                                                  const float* __restrict__ f2b,
                                                  const float* __restrict__ bn1g,
                                                  const float* __restrict__ bn1b) {
    __shared__ float sF1[64 * 128];  // 32 KB
    __shared__ float sH[8][64];
    __shared__ float sT[8][128];
    __shared__ float sMu[64], sRs[64], sG[64], sB[64], sB1[128];
    __shared__ float ssum[64], ssq[64];
    int t = threadIdx.x;
    for (int i = t; i < 8192; i += 256) sF1[i] = f1w[i];
    if (t < 64) {
        float su = g_stats[t], sq = g_stats[64 + t];
        float mu = su * (1.0f / NN);
        float var = sq * (1.0f / NN) - mu * mu;
        sMu[t] = mu;
        sRs[t] = rsqrtf(var + 1e-5f);
        sG[t] = bn1g[t];
        sB[t] = bn1b[t];
        ssum[t] = 0.0f;
        ssq[t] = 0.0f;
    }
    if (t < 128) sB1[t] = f1b[t];
    __syncthreads();
    int jg = t & 31, nn = t >> 5;  // nn: node slot 0..7
    float2 f2bv = ((const float2*)f2b)[jg];
    const ulonglong2* F1 = (const ulonglong2*)sF1;
    const unsigned long long* F2 = (const unsigned long long*)f2w;
    float2 ls = make_float2(0, 0), lq = make_float2(0, 0);
    for (int base = blockIdx.x * 8; base < NN; base += gridDim.x * 8) {
#pragma unroll
        for (int ii = 0; ii < 2; ii++) {
            int idx = t + ii * 256;
            int n = idx >> 6, c = idx & 63;
            float hv = g_h1[(base + n) * 64 + c];
            sH[n][c] = sG[c] * (hv - sMu[c]) * sRs[c] + sB[c];
        }
        __syncthreads();
        {
            unsigned long long a01 = 0ull, a23 = 0ull;
#pragma unroll
            for (int k = 0; k < 64; k++) {
                unsigned long long xx = pack2(sH[nn][k]);
                ulonglong2 w = F1[k * 32 + jg];
                fma2(a01, w.x, xx);
                fma2(a23, w.y, xx);
            }
            float2 lo = unpack2(a01), hi = unpack2(a23);
            int j0 = jg * 4;
            float4 tv;
            tv.x = fmaxf(lo.x + sB1[j0 + 0], 0.0f);
            tv.y = fmaxf(lo.y + sB1[j0 + 1], 0.0f);
            tv.z = fmaxf(hi.x + sB1[j0 + 2], 0.0f);
            tv.w = fmaxf(hi.y + sB1[j0 + 3], 0.0f);
            *(float4*)&sT[nn][j0] = tv;
        }
        __syncthreads();
        {
            unsigned long long a01 = 0ull;
#pragma unroll
            for (int k = 0; k < 128; k++) {
                unsigned long long xx = pack2(sT[nn][k]);
                fma2(a01, F2[k * 32 + jg], xx);
            }
            float2 o = unpack2(a01);
            int col = jg * 2;
            float2 hb = *(float2*)&sH[nn][col];
            o.x += f2bv.x + hb.x;
            o.y += f2bv.y + hb.y;
            *(float2*)&g_h2[(base + nn) * 64 + col] = o;
            ls.x += o.x; ls.y += o.y;
            lq.x += o.x * o.x; lq.y += o.y * o.y;
        }
        __syncthreads();
    }
    int col = jg * 2;
    atomicAdd(&ssum[col], ls.x);     atomicAdd(&ssum[col + 1], ls.y);
    atomicAdd(&ssq[col], lq.x);      atomicAdd(&ssq[col + 1], lq.y);
    __syncthreads();
    if (t < 64) {
        atomicAdd(&g_stats[128 + t], ssum[t]);
        atomicAdd(&g_stats[192 + t], ssq[t]);
    }
}

// ---------------- BN2 apply -> output ----------------
__global__ __launch_bounds__(256) void bn2_kernel(const float* __restrict__ bn2g,
                                                  const float* __restrict__ bn2b,
                                                  float* __restrict__ out) {
    int tid = blockIdx.x * 256 + threadIdx.x;  // over NN*16 float4 groups
    int i = tid & 15;
    int c0 = i * 4;
    float4 g = ((const float4*)bn2g)[i];
    float4 b = ((const float4*)bn2b)[i];
    float4 v = ((const float4*)g_h2)[tid];
    float4 o;
#pragma unroll
    for (int j = 0; j < 4; j++) {
        int c = c0 + j;
        float mu = g_stats[128 + c] * (1.0f / NN);
        float var = g_stats[192 + c] * (1.0f / NN) - mu * mu;
        float rs = rsqrtf(var + 1e-5f);
        float* vp = (&v.x) + j;
        float* op = (&o.x) + j;
        float* gp = (&g.x) + j;
        float* bp = (&b.x) + j;
        *op = (*gp) * ((*vp) - mu) * rs + (*bp);
    }
    ((float4*)out)[tid] = o;
}

// ---------------- host launcher ----------------
extern "C" void kernel_launch(void* const* d_in, const int* in_sizes, int n_in,
                              void* d_out, int out_size) {
    const float *x = nullptr, *edge_attr = nullptr;
    const float *Wq = nullptr, *Wk = nullptr, *We = nullptr, *Wv = nullptr, *Ow = nullptr;
    const float *Ob = nullptr, *f1w = nullptr, *f1b = nullptr, *f2w = nullptr, *f2b = nullptr;
    const float *bn1g = nullptr, *bn1b = nullptr, *bn2g = nullptr, *bn2b = nullptr;
    const int* ei = nullptr;
    int c4096 = 0, c8192 = 0, c64 = 0;
    for (int i = 0; i < n_in; i++) {
        int s = in_sizes[i];
        const void* p = d_in[i];
        if (s == NN * 64) x = (const float*)p;
        else if (s == EE * 64) edge_attr = (const float*)p;
        else if (s == 2 * EE) ei = (const int*)p;
        else if (s == 4096) {
            const float* f = (const float*)p;
            if (c4096 == 0) Wq = f;
            else if (c4096 == 1) Wk = f;
            else if (c4096 == 2) We = f;
            else if (c4096 == 3) Wv = f;
            else Ow = f;
            c4096++;
        } else if (s == 8192) {
            if (c8192 == 0) f1w = (const float*)p;
            else f2w = (const float*)p;
            c8192++;
        } else if (s == 128) {
            f1b = (const float*)p;
        } else if (s == 64) {
            const float* f = (const float*)p;
            if (c64 == 0) Ob = f;
            else if (c64 == 1) f2b = f;
            else if (c64 == 2) bn1g = f;
            else if (c64 == 3) bn1b = f;
            else if (c64 == 4) bn2g = f;
            else bn2b = f;
            c64++;
        }
    }

    zero_kernel<<<1184, 256>>>();
    qkv_kernel<<<391, 128>>>(x, Wq, Wk, Wv);
    edge_fused_kernel<<<6250, 128>>>(edge_attr, We, ei);
    znorm_kernel<<<1563, 256>>>();
    attn_out_kernel<<<391, 128>>>(x, Ow, Ob);
    stats1_kernel<<<296, 256>>>();
    ffn_kernel<<<1184, 256>>>(f1w, f1b, f2w, f2b, bn1g, bn1b);
    bn2_kernel<<<3125, 256>>>(bn2g, bn2b, (float*)d_out);
}

// round 3
// speedup vs baseline: 2.0853x; 1.0634x over previous
#include <cuda_runtime.h>

#define NN 50000
#define EE 800000
// dims: IN=OUT=64, H=8, HD=8

// ---------------- device scratch (allocation-free) ----------------
__device__ float g_Q[NN * 64];
__device__ float g_K[NN * 64];
__device__ float g_V[NN * 64];
__device__ float g_wV[NN * 64];       // normalized attn output (written once by agg)
__device__ float g_sc[EE * 8];        // per-edge per-head exp score
__device__ float g_t[NN * 128];       // FFN hidden
__device__ float g_h1[NN * 64];       // pre-BN1 (x + attn@O_w + O_b)
__device__ float g_h2[NN * 64];       // pre-BN2 (bn1_out + ffn)
__device__ float g_stats[256];        // [sum1|sumsq1|sum2|sumsq2] x64
__device__ int   g_cnt[NN];
__device__ int   g_off[NN + 1];
__device__ int   g_cur[NN];
__device__ int   g_part[256];
__device__ int   g_perm[EE];

// ---------------- f32x2 helpers ----------------
__device__ __forceinline__ unsigned long long pack2(float v) {
    unsigned long long r;
    asm("mov.b64 %0, {%1, %1};" : "=l"(r) : "f"(v));
    return r;
}
__device__ __forceinline__ void fma2(unsigned long long& acc, unsigned long long a,
                                     unsigned long long b) {
    asm("fma.rn.f32x2 %0, %1, %2, %0;" : "+l"(acc) : "l"(a), "l"(b));
}
__device__ __forceinline__ float2 unpack2(unsigned long long v) {
    float2 r;
    asm("mov.b64 {%0, %1}, %2;" : "=f"(r.x), "=f"(r.y) : "l"(v));
    return r;
}

// Pair-swizzled weight staging: float4 chunk q of row k -> slot k*16+(q&1)*8+(q>>1).
// Lane lc reads its 8 cols (lc*8..+7) as ulonglong2 at slots k*16+lc and k*16+8+lc,
// each 128B-contiguous across the 8 lanes (conflict-free).
__device__ __forceinline__ void stage_weight(float* sW, const float* W, int t, int nthr,
                                             int nrows) {
    const float4* W4 = (const float4*)W;
    float4* sW4 = (float4*)sW;
    for (int i = t; i < nrows * 16; i += nthr) {
        int k = i >> 4, q = i & 15;
        sW4[k * 16 + (q & 1) * 8 + (q >> 1)] = W4[i];
    }
}
// Stage a 64-col half of a 64x128 matrix (row stride 32 float4s).
__device__ __forceinline__ void stage_weight_half(float* sW, const float* W, int half,
                                                  int t, int nthr) {
    const float4* W4 = (const float4*)W;
    float4* sW4 = (float4*)sW;
    for (int i = t; i < 1024; i += nthr) {
        int k = i >> 4, q = i & 15;
        sW4[k * 16 + (q & 1) * 8 + (q >> 1)] = W4[k * 32 + half * 16 + q];
    }
}

// ---------------- 256-thread exclusive block scan ----------------
__device__ __forceinline__ int block_excl_scan_256(int v, int t, int* smem8) {
    unsigned lane = t & 31;
    int w = t >> 5;
    int x = v;
#pragma unroll
    for (int d = 1; d < 32; d <<= 1) {
        int y = __shfl_up_sync(0xffffffffu, x, d);
        if ((int)lane >= d) x += y;
    }
    if (lane == 31) smem8[w] = x;
    __syncthreads();
    if (t == 0) {
        int run = 0;
#pragma unroll
        for (int i = 0; i < 8; i++) { int c = smem8[i]; smem8[i] = run; run += c; }
    }
    __syncthreads();
    return x - v + smem8[w];
}

// ---------------- zero counters/stats ----------------
__global__ __launch_bounds__(256) void zero_kernel() {
    int idx = blockIdx.x * 256 + threadIdx.x;
    if (idx < NN) g_cnt[idx] = 0;
    if (idx < 256) g_stats[idx] = 0.0f;
}

// ---------------- CSR build: count, scan, bin ----------------
__global__ __launch_bounds__(256) void count_kernel(const int* __restrict__ ei) {
    int e = blockIdx.x * 256 + threadIdx.x;
    if (e < EE) atomicAdd(&g_cnt[ei[EE + e]], 1);
}
__global__ __launch_bounds__(256) void scan_part_kernel() {
    __shared__ int s8[8];
    int t = threadIdx.x;
    int i = blockIdx.x * 256 + t;
    int v = (i < NN) ? g_cnt[i] : 0;
    int ex = block_excl_scan_256(v, t, s8);
    if (t == 255) g_part[blockIdx.x] = ex + v;
}
__global__ __launch_bounds__(256) void scan_mid_kernel(int nparts) {
    __shared__ int s8[8];
    int t = threadIdx.x;
    int v = (t < nparts) ? g_part[t] : 0;
    int ex = block_excl_scan_256(v, t, s8);
    if (t < nparts) g_part[t] = ex;
}
__global__ __launch_bounds__(256) void scan_write_kernel() {
    __shared__ int s8[8];
    int t = threadIdx.x;
    int i = blockIdx.x * 256 + t;
    int v = (i < NN) ? g_cnt[i] : 0;
    int ex = block_excl_scan_256(v, t, s8) + g_part[blockIdx.x];
    if (i < NN) { g_off[i] = ex; g_cur[i] = ex; }
    if (i == NN - 1) g_off[NN] = ex + v;
}
__global__ __launch_bounds__(256) void bin_kernel(const int* __restrict__ ei) {
    int e = blockIdx.x * 256 + threadIdx.x;
    if (e < EE) {
        int pos = atomicAdd(&g_cur[ei[EE + e]], 1);
        g_perm[pos] = e;
    }
}

// ---------------- fused Q/K/V projection (warp-tiled GEMM) ----------------
__global__ __launch_bounds__(128, 3) void qkv_kernel(const float* __restrict__ x,
                                                     const float* __restrict__ Wq,
                                                     const float* __restrict__ Wk,
                                                     const float* __restrict__ Wv) {
    __shared__ float sW[3][4096];
    int t = threadIdx.x;
    stage_weight(sW[0], Wq, t, 128, 64);
    stage_weight(sW[1], Wk, t, 128, 64);
    stage_weight(sW[2], Wv, t, 128, 64);
    __syncthreads();
    int warp = t >> 5, lane = t & 31;
    int lr = lane >> 3, lc = lane & 7;
    int tile = blockIdx.x * 4 + warp;
    if (tile >= (NN + 31) / 32) return;
    int row0 = tile * 32 + lr * 8;
    const float4* A4 = (const float4*)x;
    for (int wsel = 0; wsel < 3; wsel++) {
        float* C = (wsel == 0) ? g_Q : (wsel == 1) ? g_K : g_V;
        const ulonglong2* sWu = (const ulonglong2*)sW[wsel];
        unsigned long long acc[8][4] = {};
        for (int kc = 0; kc < 64; kc += 4) {
            float4 a[8];
#pragma unroll
            for (int i = 0; i < 8; i++) {
                int r = row0 + i;
                a[i] = (r < NN) ? A4[r * 16 + (kc >> 2)] : make_float4(0, 0, 0, 0);
            }
#pragma unroll
            for (int kk = 0; kk < 4; kk++) {
                ulonglong2 wlo = sWu[(kc + kk) * 16 + lc];
                ulonglong2 whi = sWu[(kc + kk) * 16 + 8 + lc];
#pragma unroll
                for (int i = 0; i < 8; i++) {
                    unsigned long long ax = pack2((&a[i].x)[kk]);
                    fma2(acc[i][0], wlo.x, ax);
                    fma2(acc[i][1], wlo.y, ax);
                    fma2(acc[i][2], whi.x, ax);
                    fma2(acc[i][3], whi.y, ax);
                }
            }
        }
#pragma unroll
        for (int i = 0; i < 8; i++) {
            int r = row0 + i;
            if (r < NN) {
                float2 c01 = unpack2(acc[i][0]), c23 = unpack2(acc[i][1]);
                float2 c45 = unpack2(acc[i][2]), c67 = unpack2(acc[i][3]);
                ((float4*)C)[r * 16 + lc * 2] = make_float4(c01.x, c01.y, c23.x, c23.y);
                ((float4*)C)[r * 16 + lc * 2 + 1] = make_float4(c45.x, c45.y, c67.x, c67.y);
            }
        }
    }
}

// ---------------- edge score kernel: Eh GEMM + score -> g_sc ----------------
// Warp tile = 32 edges x 64 cols; lane = 8 edges x head lc (8 cols).
__global__ __launch_bounds__(128, 3) void score_kernel(const float* __restrict__ EA,
                                                       const float* __restrict__ We,
                                                       const int* __restrict__ ei) {
    __shared__ float sW[4096];
    int t = threadIdx.x;
    stage_weight(sW, We, t, 128, 64);
    __syncthreads();
    int warp = t >> 5, lane = t & 31;
    int lr = lane >> 3, lc = lane & 7;
    int tile = blockIdx.x * 4 + warp;   // 25000 tiles exactly
    int e0 = tile * 32 + lr * 8;
    const ulonglong2* sWu = (const ulonglong2*)sW;
    const float4* A4 = (const float4*)EA;
    unsigned long long acc[8][4] = {};
    for (int kc = 0; kc < 64; kc += 4) {
        float4 a[8];
#pragma unroll
        for (int i = 0; i < 8; i++) a[i] = A4[(e0 + i) * 16 + (kc >> 2)];
#pragma unroll
        for (int kk = 0; kk < 4; kk++) {
            ulonglong2 wlo = sWu[(kc + kk) * 16 + lc];
            ulonglong2 whi = sWu[(kc + kk) * 16 + 8 + lc];
#pragma unroll
            for (int i = 0; i < 8; i++) {
                unsigned long long ax = pack2((&a[i].x)[kk]);
                fma2(acc[i][0], wlo.x, ax);
                fma2(acc[i][1], wlo.y, ax);
                fma2(acc[i][2], whi.x, ax);
                fma2(acc[i][3], whi.y, ax);
            }
        }
    }
    const float4* K4 = (const float4*)g_K;
    const float4* Q4 = (const float4*)g_Q;
    const float inv = 0.35355339059327373f;  // 1/sqrt(8)
#pragma unroll
    for (int i = 0; i < 8; i++) {
        int e = e0 + i;
        int src = ei[e];
        int dst = ei[EE + e];
        float2 e01 = unpack2(acc[i][0]), e23 = unpack2(acc[i][1]);
        float2 e45 = unpack2(acc[i][2]), e67 = unpack2(acc[i][3]);
        float4 kk0 = K4[src * 16 + lc * 2], kk1 = K4[src * 16 + lc * 2 + 1];
        float4 qq0 = Q4[dst * 16 + lc * 2], qq1 = Q4[dst * 16 + lc * 2 + 1];
        float s = e01.x * kk0.x * qq0.x + e01.y * kk0.y * qq0.y
                + e23.x * kk0.z * qq0.z + e23.y * kk0.w * qq0.w
                + e45.x * kk1.x * qq1.x + e45.y * kk1.y * qq1.y
                + e67.x * kk1.z * qq1.z + e67.y * kk1.w * qq1.w;
        s = fminf(fmaxf(s * inv, -5.0f), 5.0f);
        g_sc[e * 8 + lc] = __expf(s);
    }
}

// ---------------- per-dst aggregation (no atomics): warp per node ----------------
__global__ __launch_bounds__(256) void agg_kernel(const int* __restrict__ ei) {
    int t = threadIdx.x;
    int w = t >> 5, lane = t & 31;
    int lr = lane >> 3, lc = lane & 7;
    int n = blockIdx.x * 8 + w;   // grid 6250 * 8 = 50000 exactly
    int beg = g_off[n], end = g_off[n + 1];
    const float4* V4 = (const float4*)g_V;
    float acc[8] = {0, 0, 0, 0, 0, 0, 0, 0};
    float zacc = 0.0f;
    for (int i = beg + lr; i < end; i += 4) {
        int e = g_perm[i];
        int src = ei[e];
        float s = g_sc[e * 8 + lc];
        float4 v0 = V4[src * 16 + lc * 2];
        float4 v1 = V4[src * 16 + lc * 2 + 1];
        acc[0] += v0.x * s; acc[1] += v0.y * s; acc[2] += v0.z * s; acc[3] += v0.w * s;
        acc[4] += v1.x * s; acc[5] += v1.y * s; acc[6] += v1.z * s; acc[7] += v1.w * s;
        zacc += s;
    }
#pragma unroll
    for (int j = 0; j < 8; j++) {
        acc[j] += __shfl_xor_sync(0xffffffffu, acc[j], 8);
        acc[j] += __shfl_xor_sync(0xffffffffu, acc[j], 16);
    }
    zacc += __shfl_xor_sync(0xffffffffu, zacc, 8);
    zacc += __shfl_xor_sync(0xffffffffu, zacc, 16);
    if (lr == 0) {
        float zi = 1.0f / (zacc + 1e-6f);
        ((float4*)g_wV)[n * 16 + lc * 2] =
            make_float4(acc[0] * zi, acc[1] * zi, acc[2] * zi, acc[3] * zi);
        ((float4*)g_wV)[n * 16 + lc * 2 + 1] =
            make_float4(acc[4] * zi, acc[5] * zi, acc[6] * zi, acc[7] * zi);
    }
}

// ---------------- O projection + residual -> g_h1 ----------------
__global__ __launch_bounds__(128, 3) void attn_out_kernel(const float* __restrict__ x,
                                                          const float* __restrict__ Ow,
                                                          const float* __restrict__ Ob) {
    __shared__ float sW[4096];
    int t = threadIdx.x;
    stage_weight(sW, Ow, t, 128, 64);
    __syncthreads();
    int warp = t >> 5, lane = t & 31;
    int lr = lane >> 3, lc = lane & 7;
    int tile = blockIdx.x * 4 + warp;
    if (tile >= (NN + 31) / 32) return;
    int row0 = tile * 32 + lr * 8;
    const ulonglong2* sWu = (const ulonglong2*)sW;
    const float4* A4 = (const float4*)g_wV;
    unsigned long long acc[8][4] = {};
    for (int kc = 0; kc < 64; kc += 4) {
        float4 a[8];
#pragma unroll
        for (int i = 0; i < 8; i++) {
            int r = row0 + i;
            a[i] = (r < NN) ? A4[r * 16 + (kc >> 2)] : make_float4(0, 0, 0, 0);
        }
#pragma unroll
        for (int kk = 0; kk < 4; kk++) {
            ulonglong2 wlo = sWu[(kc + kk) * 16 + lc];
            ulonglong2 whi = sWu[(kc + kk) * 16 + 8 + lc];
#pragma unroll
            for (int i = 0; i < 8; i++) {
                unsigned long long ax = pack2((&a[i].x)[kk]);
                fma2(acc[i][0], wlo.x, ax);
                fma2(acc[i][1], wlo.y, ax);
                fma2(acc[i][2], whi.x, ax);
                fma2(acc[i][3], whi.y, ax);
            }
        }
    }
    float4 ob0 = ((const float4*)Ob)[lc * 2];
    float4 ob1 = ((const float4*)Ob)[lc * 2 + 1];
    const float4* x4 = (const float4*)x;
#pragma unroll
    for (int i = 0; i < 8; i++) {
        int r = row0 + i;
        if (r < NN) {
            float2 c01 = unpack2(acc[i][0]), c23 = unpack2(acc[i][1]);
            float2 c45 = unpack2(acc[i][2]), c67 = unpack2(acc[i][3]);
            float4 xa = x4[r * 16 + lc * 2], xb = x4[r * 16 + lc * 2 + 1];
            ((float4*)g_h1)[r * 16 + lc * 2] =
                make_float4(c01.x + ob0.x + xa.x, c01.y + ob0.y + xa.y,
                            c23.x + ob0.z + xa.z, c23.y + ob0.w + xa.w);
            ((float4*)g_h1)[r * 16 + lc * 2 + 1] =
                make_float4(c45.x + ob1.x + xb.x, c45.y + ob1.y + xb.y,
                            c67.x + ob1.z + xb.z, c67.y + ob1.w + xb.w);
        }
    }
}

// ---------------- BN1 stats over g_h1 ----------------
__global__ __launch_bounds__(256) void stats1_kernel() {
    __shared__ float ssum[64], ssq[64];
    int t = threadIdx.x;
    if (t < 64) { ssum[t] = 0.0f; ssq[t] = 0.0f; }
    __syncthreads();
    int cg = t & 15;
    float4 s = make_float4(0, 0, 0, 0), q = make_float4(0, 0, 0, 0);
    for (int r = blockIdx.x * 16 + (t >> 4); r < NN; r += gridDim.x * 16) {
        float4 v = ((const float4*)g_h1)[r * 16 + cg];
        s.x += v.x; s.y += v.y; s.z += v.z; s.w += v.w;
        q.x += v.x * v.x; q.y += v.y * v.y; q.z += v.z * v.z; q.w += v.w * v.w;
    }
    int c0 = cg * 4;
    atomicAdd(&ssum[c0 + 0], s.x); atomicAdd(&ssum[c0 + 1], s.y);
    atomicAdd(&ssum[c0 + 2], s.z); atomicAdd(&ssum[c0 + 3], s.w);
    atomicAdd(&ssq[c0 + 0], q.x);  atomicAdd(&ssq[c0 + 1], q.y);
    atomicAdd(&ssq[c0 + 2], q.z);  atomicAdd(&ssq[c0 + 3], q.w);
    __syncthreads();
    if (t < 64) {
        atomicAdd(&g_stats[t], ssum[t]);
        atomicAdd(&g_stats[64 + t], ssq[t]);
    }
}

// ---------------- FFN part A: t = relu(BN1(h1) @ f1_w + f1_b) ----------------
__global__ __launch_bounds__(128, 3) void ffnA_kernel(const float* __restrict__ f1w,
                                                      const float* __restrict__ f1b,
                                                      const float* __restrict__ bn1g,
                                                      const float* __restrict__ bn1b) {
    __shared__ float sW[2][4096];
    __shared__ float sScale[64], sShift[64], sB1[128];
    int t = threadIdx.x;
    stage_weight_half(sW[0], f1w, 0, t, 128);
    stage_weight_half(sW[1], f1w, 1, t, 128);
    if (t < 64) {
        float mu = g_stats[t] * (1.0f / NN);
        float var = g_stats[64 + t] * (1.0f / NN) - mu * mu;
        float sc = bn1g[t] * rsqrtf(var + 1e-5f);
        sScale[t] = sc;
        sShift[t] = bn1b[t] - mu * sc;
    }
    if (t < 128) sB1[t] = f1b[t];
    __syncthreads();
    int warp = t >> 5, lane = t & 31;
    int lr = lane >> 3, lc = lane & 7;
    int tile = blockIdx.x * 4 + warp;
    if (tile >= (NN + 31) / 32) return;
    int row0 = tile * 32 + lr * 8;
    const float4* A4 = (const float4*)g_h1;
    for (int h = 0; h < 2; h++) {
        const ulonglong2* sWu = (const ulonglong2*)sW[h];
        unsigned long long acc[8][4] = {};
        for (int kc = 0; kc < 64; kc += 4) {
            float4 scl = *(const float4*)&sScale[kc];
            float4 shf = *(const float4*)&sShift[kc];
            float4 a[8];
#pragma unroll
            for (int i = 0; i < 8; i++) {
                int r = row0 + i;
                float4 v = (r < NN) ? A4[r * 16 + (kc >> 2)] : make_float4(0, 0, 0, 0);
                a[i] = make_float4(v.x * scl.x + shf.x, v.y * scl.y + shf.y,
                                   v.z * scl.z + shf.z, v.w * scl.w + shf.w);
            }
#pragma unroll
            for (int kk = 0; kk < 4; kk++) {
                ulonglong2 wlo = sWu[(kc + kk) * 16 + lc];
                ulonglong2 whi = sWu[(kc + kk) * 16 + 8 + lc];
#pragma unroll
                for (int i = 0; i < 8; i++) {
                    unsigned long long ax = pack2((&a[i].x)[kk]);
                    fma2(acc[i][0], wlo.x, ax);
                    fma2(acc[i][1], wlo.y, ax);
                    fma2(acc[i][2], whi.x, ax);
                    fma2(acc[i][3], whi.y, ax);
                }
            }
        }
        int j0 = h * 64 + lc * 8;
        float4 b0 = *(const float4*)&sB1[j0];
        float4 b1 = *(const float4*)&sB1[j0 + 4];
#pragma unroll
        for (int i = 0; i < 8; i++) {
            int r = row0 + i;
            if (r < NN) {
                float2 c01 = unpack2(acc[i][0]), c23 = unpack2(acc[i][1]);
                float2 c45 = unpack2(acc[i][2]), c67 = unpack2(acc[i][3]);
                float4 t0 = make_float4(fmaxf(c01.x + b0.x, 0.0f), fmaxf(c01.y + b0.y, 0.0f),
                                        fmaxf(c23.x + b0.z, 0.0f), fmaxf(c23.y + b0.w, 0.0f));
                float4 t1 = make_float4(fmaxf(c45.x + b1.x, 0.0f), fmaxf(c45.y + b1.y, 0.0f),
                                        fmaxf(c67.x + b1.z, 0.0f), fmaxf(c67.y + b1.w, 0.0f));
                ((float4*)g_t)[r * 32 + h * 16 + lc * 2] = t0;
                ((float4*)g_t)[r * 32 + h * 16 + lc * 2 + 1] = t1;
            }
        }
    }
}

// ---------------- FFN part B: h2 = t @ f2_w + f2_b + BN1(h1), + BN2 stats ----------
__global__ __launch_bounds__(128, 3) void ffnB_kernel(const float* __restrict__ f2w,
                                                      const float* __restrict__ f2b,
                                                      const float* __restrict__ bn1g,
                                                      const float* __restrict__ bn1b) {
    __shared__ float sW[8192];   // 128x64
    __shared__ float sScale[64], sShift[64], sF2b[64];
    __shared__ float ssum[64], ssq[64];
    int t = threadIdx.x;
    stage_weight(sW, f2w, t, 128, 128);
    if (t < 64) {
        float mu = g_stats[t] * (1.0f / NN);
        float var = g_stats[64 + t] * (1.0f / NN) - mu * mu;
        float sc = bn1g[t] * rsqrtf(var + 1e-5f);
        sScale[t] = sc;
        sShift[t] = bn1b[t] - mu * sc;
        sF2b[t] = f2b[t];
        ssum[t] = 0.0f;
        ssq[t] = 0.0f;
    }
    __syncthreads();
    int warp = t >> 5, lane = t & 31;
    int lr = lane >> 3, lc = lane & 7;
    int tile = blockIdx.x * 4 + warp;
    float ls[8] = {0, 0, 0, 0, 0, 0, 0, 0}, lq[8] = {0, 0, 0, 0, 0, 0, 0, 0};
    if (tile < (NN + 31) / 32) {
        int row0 = tile * 32 + lr * 8;
        const ulonglong2* sWu = (const ulonglong2*)sW;
        const float4* T4 = (const float4*)g_t;
        unsigned long long acc[8][4] = {};
        for (int kc = 0; kc < 128; kc += 4) {
            float4 a[8];
#pragma unroll
            for (int i = 0; i < 8; i++) {
                int r = row0 + i;
                a[i] = (r < NN) ? T4[r * 32 + (kc >> 2)] : make_float4(0, 0, 0, 0);
            }
#pragma unroll
            for (int kk = 0; kk < 4; kk++) {
                ulonglong2 wlo = sWu[(kc + kk) * 16 + lc];
                ulonglong2 whi = sWu[(kc + kk) * 16 + 8 + lc];
#pragma unroll
                for (int i = 0; i < 8; i++) {
                    unsigned long long ax = pack2((&a[i].x)[kk]);
                    fma2(acc[i][0], wlo.x, ax);
                    fma2(acc[i][1], wlo.y, ax);
                    fma2(acc[i][2], whi.x, ax);
                    fma2(acc[i][3], whi.y, ax);
                }
            }
        }
        int j0 = lc * 8;
        float4 fb0 = *(const float4*)&sF2b[j0];
        float4 fb1 = *(const float4*)&sF2b[j0 + 4];
        float4 sc0 = *(const float4*)&sScale[j0];
        float4 sc1 = *(const float4*)&sScale[j0 + 4];
        float4 sh0 = *(const float4*)&sShift[j0];
        float4 sh1 = *(const float4*)&sShift[j0 + 4];
        const float4* H4 = (const float4*)g_h1;
#pragma unroll
        for (int i = 0; i < 8; i++) {
            int r = row0 + i;
            if (r < NN) {
                float2 c01 = unpack2(acc[i][0]), c23 = unpack2(acc[i][1]);
                float2 c45 = unpack2(acc[i][2]), c67 = unpack2(acc[i][3]);
                float4 h0 = H4[r * 16 + lc * 2], h1v = H4[r * 16 + lc * 2 + 1];
                float4 o0, o1;
                o0.x = c01.x + fb0.x + h0.x * sc0.x + sh0.x;
                o0.y = c01.y + fb0.y + h0.y * sc0.y + sh0.y;
                o0.z = c23.x + fb0.z + h0.z * sc0.z + sh0.z;
                o0.w = c23.y + fb0.w + h0.w * sc0.w + sh0.w;
                o1.x = c45.x + fb1.x + h1v.x * sc1.x + sh1.x;
                o1.y = c45.y + fb1.y + h1v.y * sc1.y + sh1.y;
                o1.z = c67.x + fb1.z + h1v.z * sc1.z + sh1.z;
                o1.w = c67.y + fb1.w + h1v.w * sc1.w + sh1.w;
                ((float4*)g_h2)[r * 16 + lc * 2] = o0;
                ((float4*)g_h2)[r * 16 + lc * 2 + 1] = o1;
                ls[0] += o0.x; ls[1] += o0.y; ls[2] += o0.z; ls[3] += o0.w;
                ls[4] += o1.x; ls[5] += o1.y; ls[6] += o1.z; ls[7] += o1.w;
                lq[0] += o0.x * o0.x; lq[1] += o0.y * o0.y;
                lq[2] += o0.z * o0.z; lq[3] += o0.w * o0.w;
                lq[4] += o1.x * o1.x; lq[5] += o1.y * o1.y;
                lq[6] += o1.z * o1.z; lq[7] += o1.w * o1.w;
            }
        }
    }
#pragma unroll
    for (int j = 0; j < 8; j++) {
        atomicAdd(&ssum[lc * 8 + j], ls[j]);
        atomicAdd(&ssq[lc * 8 + j], lq[j]);
    }
    __syncthreads();
    if (t < 64) {
        atomicAdd(&g_stats[128 + t], ssum[t]);
        atomicAdd(&g_stats[192 + t], ssq[t]);
    }
}

// ---------------- BN2 apply -> output ----------------
__global__ __launch_bounds__(256) void bn2_kernel(const float* __restrict__ bn2g,
                                                  const float* __restrict__ bn2b,
                                                  float* __restrict__ out) {
    int tid = blockIdx.x * 256 + threadIdx.x;  // over NN*16 float4 groups
    int i = tid & 15;
    int c0 = i * 4;
    float4 g = ((const float4*)bn2g)[i];
    float4 b = ((const float4*)bn2b)[i];
    float4 v = ((const float4*)g_h2)[tid];
    float4 o;
#pragma unroll
    for (int j = 0; j < 4; j++) {
        int c = c0 + j;
        float mu = g_stats[128 + c] * (1.0f / NN);
        float var = g_stats[192 + c] * (1.0f / NN) - mu * mu;
        float rs = rsqrtf(var + 1e-5f);
        (&o.x)[j] = (&g.x)[j] * ((&v.x)[j] - mu) * rs + (&b.x)[j];
    }
    ((float4*)out)[tid] = o;
}

// ---------------- host launcher ----------------
extern "C" void kernel_launch(void* const* d_in, const int* in_sizes, int n_in,
                              void* d_out, int out_size) {
    const float *x = nullptr, *edge_attr = nullptr;
    const float *Wq = nullptr, *Wk = nullptr, *We = nullptr, *Wv = nullptr, *Ow = nullptr;
    const float *Ob = nullptr, *f1w = nullptr, *f1b = nullptr, *f2w = nullptr, *f2b = nullptr;
    const float *bn1g = nullptr, *bn1b = nullptr, *bn2g = nullptr, *bn2b = nullptr;
    const int* ei = nullptr;
    int c4096 = 0, c8192 = 0, c64 = 0;
    for (int i = 0; i < n_in; i++) {
        int s = in_sizes[i];
        const void* p = d_in[i];
        if (s == NN * 64) x = (const float*)p;
        else if (s == EE * 64) edge_attr = (const float*)p;
        else if (s == 2 * EE) ei = (const int*)p;
        else if (s == 4096) {
            const float* f = (const float*)p;
            if (c4096 == 0) Wq = f;
            else if (c4096 == 1) Wk = f;
            else if (c4096 == 2) We = f;
            else if (c4096 == 3) Wv = f;
            else Ow = f;
            c4096++;
        } else if (s == 8192) {
            if (c8192 == 0) f1w = (const float*)p;
            else f2w = (const float*)p;
            c8192++;
        } else if (s == 128) {
            f1b = (const float*)p;
        } else if (s == 64) {
            const float* f = (const float*)p;
            if (c64 == 0) Ob = f;
            else if (c64 == 1) f2b = f;
            else if (c64 == 2) bn1g = f;
            else if (c64 == 3) bn1b = f;
            else if (c64 == 4) bn2g = f;
            else bn2b = f;
            c64++;
        }
    }

    const int NPART = (NN + 255) / 256;  // 196

    zero_kernel<<<NPART, 256>>>();
    count_kernel<<<(EE + 255) / 256, 256>>>(ei);
    scan_part_kernel<<<NPART, 256>>>();
    scan_mid_kernel<<<1, 256>>>(NPART);
    scan_write_kernel<<<NPART, 256>>>();
    bin_kernel<<<(EE + 255) / 256, 256>>>(ei);
    qkv_kernel<<<391, 128>>>(x, Wq, Wk, Wv);
    score_kernel<<<6250, 128>>>(edge_attr, We, ei);
    agg_kernel<<<6250, 256>>>(ei);
    attn_out_kernel<<<391, 128>>>(x, Ow, Ob);
    stats1_kernel<<<296, 256>>>();
    ffnA_kernel<<<391, 128>>>(f1w, f1b, bn1g, bn1b);
    ffnB_kernel<<<391, 128>>>(f2w, f2b, bn1g, bn1b);
    bn2_kernel<<<3125, 256>>>(bn2g, bn2b, (float*)d_out);
}